// round 2
// baseline (speedup 1.0000x reference)
#include <cuda_runtime.h>

#define SEQ_LEN   8192
#define STATE_LEN 4096
#define T_DIM     1024
#define THREADS   256
#define ITERS     8          // 8 iters x float4 x 256 threads = 8192 cols

// 32 MB scratch: softmax table, one row per distinct time index t.
__device__ float g_soft[(size_t)T_DIM * SEQ_LEN];

// ---------------- Kernel A: softmax table over all 1024 t values ----------------
__global__ __launch_bounds__(THREADS)
void softmax_table_kernel(const int* __restrict__ his,
                          const float* __restrict__ tsm)
{
    __shared__ float row[T_DIM];
    __shared__ float red_max[THREADS / 32];
    __shared__ float red_sum[THREADS / 32];

    const int tid = threadIdx.x;
    const int t   = blockIdx.x;

    // load tsm[t, :] (4 KB) into smem
    {
        const float4* src = reinterpret_cast<const float4*>(tsm + (size_t)t * T_DIM);
        reinterpret_cast<float4*>(row)[tid] = src[tid];
    }
    __syncthreads();

    // gather into registers, thread-local max
    float e[ITERS * 4];
    float m = -INFINITY;
    const int4* his4 = reinterpret_cast<const int4*>(his);
    #pragma unroll
    for (int it = 0; it < ITERS; it++) {
        int4 h = his4[it * THREADS + tid];
        float a = row[h.x];
        float b = row[h.y];
        float g = row[h.z];
        float d = row[h.w];
        e[it * 4 + 0] = a;
        e[it * 4 + 1] = b;
        e[it * 4 + 2] = g;
        e[it * 4 + 3] = d;
        m = fmaxf(m, fmaxf(fmaxf(a, b), fmaxf(g, d)));
    }

    // block max
    #pragma unroll
    for (int off = 16; off; off >>= 1)
        m = fmaxf(m, __shfl_xor_sync(0xffffffff, m, off));
    if ((tid & 31) == 0) red_max[tid >> 5] = m;
    __syncthreads();
    float bm = red_max[0];
    #pragma unroll
    for (int w = 1; w < THREADS / 32; w++) bm = fmaxf(bm, red_max[w]);

    // exp once, thread-local sum
    float s = 0.0f;
    #pragma unroll
    for (int k = 0; k < ITERS * 4; k++) {
        e[k] = __expf(e[k] - bm);
        s += e[k];
    }

    // block sum
    #pragma unroll
    for (int off = 16; off; off >>= 1)
        s += __shfl_xor_sync(0xffffffff, s, off);
    if ((tid & 31) == 0) red_sum[tid >> 5] = s;
    __syncthreads();
    float bs = 0.0f;
    #pragma unroll
    for (int w = 0; w < THREADS / 32; w++) bs += red_sum[w];
    const float inv = 1.0f / bs;

    // normalize + write table row (coalesced float4)
    float4* o = reinterpret_cast<float4*>(g_soft + (size_t)t * SEQ_LEN);
    #pragma unroll
    for (int it = 0; it < ITERS; it++) {
        float4 v;
        v.x = e[it * 4 + 0] * inv;
        v.y = e[it * 4 + 1] * inv;
        v.z = e[it * 4 + 2] * inv;
        v.w = e[it * 4 + 3] * inv;
        o[it * THREADS + tid] = v;
    }
}

// ---------------- Kernel B: replicate rows out[i,:] = g_soft[cur[i],:] ----------------
__global__ __launch_bounds__(THREADS)
void replicate_rows_kernel(const int* __restrict__ cur,
                           float* __restrict__ out)
{
    const int tid = threadIdx.x;
    const int i   = blockIdx.x;
    const int c   = cur[i];                          // broadcast load

    const float4* src = reinterpret_cast<const float4*>(g_soft + (size_t)c * SEQ_LEN);
    float4*       dst = reinterpret_cast<float4*>(out + (size_t)i * SEQ_LEN);
    #pragma unroll
    for (int it = 0; it < ITERS; it++) {
        dst[it * THREADS + tid] = src[it * THREADS + tid];
    }
}

extern "C" void kernel_launch(void* const* d_in, const int* in_sizes, int n_in,
                              void* d_out, int out_size)
{
    const int*   his = (const int*)d_in[0];    // [8192] int32
    const int*   cur = (const int*)d_in[1];    // [4096] int32
    const float* tsm = (const float*)d_in[2];  // [1024*1024] fp32
    float*       out = (float*)d_out;          // [4096*8192] fp32

    softmax_table_kernel<<<T_DIM, THREADS>>>(his, tsm);
    replicate_rows_kernel<<<STATE_LEN, THREADS>>>(cur, out);
}

// round 3
// speedup vs baseline: 1.1521x; 1.1521x over previous
#include <cuda_runtime.h>

#define SEQ_LEN   8192
#define STATE_LEN 4096
#define T_DIM     1024
#define THREADS   256
#define ITERS     8          // 8 iters x float4 x 256 threads = 8192 cols
#define CUR_PER_THREAD (STATE_LEN / THREADS)   // 16

__global__ __launch_bounds__(THREADS)
void attn_time_dedup_kernel(const int* __restrict__ his,
                            const int* __restrict__ cur,
                            const float* __restrict__ tsm,
                            float* __restrict__ out)
{
    __shared__ float row[T_DIM];                 // tsm row for this t (4 KB)
    __shared__ int   match[STATE_LEN];           // rows i with cur[i]==t (16 KB, worst case safe)
    __shared__ int   match_cnt;
    __shared__ float red_max[THREADS / 32];
    __shared__ float red_sum[THREADS / 32];

    const int tid = threadIdx.x;
    const int t   = blockIdx.x;

    if (tid == 0) match_cnt = 0;
    __syncthreads();

    // ---- phase 0: find all output rows that use this t (cur is L2-resident) ----
    #pragma unroll
    for (int k = 0; k < CUR_PER_THREAD; k++) {
        int i = k * THREADS + tid;
        if (cur[i] == t) {
            int pos = atomicAdd(&match_cnt, 1);
            match[pos] = i;
        }
    }
    __syncthreads();
    const int cnt = match_cnt;
    if (cnt == 0) return;                        // this t never referenced

    // ---- load tsm[t, :] into smem ----
    {
        const float4* src = reinterpret_cast<const float4*>(tsm + (size_t)t * T_DIM);
        reinterpret_cast<float4*>(row)[tid] = src[tid];
    }
    __syncthreads();

    // ---- gather into registers, thread-local max ----
    float e[ITERS * 4];
    float m = -INFINITY;
    const int4* his4 = reinterpret_cast<const int4*>(his);
    #pragma unroll
    for (int it = 0; it < ITERS; it++) {
        int4 h = his4[it * THREADS + tid];
        float a = row[h.x];
        float b = row[h.y];
        float g = row[h.z];
        float d = row[h.w];
        e[it * 4 + 0] = a;
        e[it * 4 + 1] = b;
        e[it * 4 + 2] = g;
        e[it * 4 + 3] = d;
        m = fmaxf(m, fmaxf(fmaxf(a, b), fmaxf(g, d)));
    }

    // ---- block max ----
    #pragma unroll
    for (int off = 16; off; off >>= 1)
        m = fmaxf(m, __shfl_xor_sync(0xffffffff, m, off));
    if ((tid & 31) == 0) red_max[tid >> 5] = m;
    __syncthreads();
    float bm = red_max[0];
    #pragma unroll
    for (int w = 1; w < THREADS / 32; w++) bm = fmaxf(bm, red_max[w]);

    // ---- exp once, thread-local sum ----
    float s = 0.0f;
    #pragma unroll
    for (int k = 0; k < ITERS * 4; k++) {
        e[k] = __expf(e[k] - bm);
        s += e[k];
    }

    // ---- block sum ----
    #pragma unroll
    for (int off = 16; off; off >>= 1)
        s += __shfl_xor_sync(0xffffffff, s, off);
    if ((tid & 31) == 0) red_sum[tid >> 5] = s;
    __syncthreads();
    float bs = 0.0f;
    #pragma unroll
    for (int w = 0; w < THREADS / 32; w++) bs += red_sum[w];
    const float inv = 1.0f / bs;

    // ---- normalize into registers once ----
    float4 v[ITERS];
    #pragma unroll
    for (int it = 0; it < ITERS; it++) {
        v[it].x = e[it * 4 + 0] * inv;
        v[it].y = e[it * 4 + 1] * inv;
        v[it].z = e[it * 4 + 2] * inv;
        v[it].w = e[it * 4 + 3] * inv;
    }

    // ---- write the same row to every matched output row ----
    for (int r = 0; r < cnt; r++) {
        float4* dst = reinterpret_cast<float4*>(out + (size_t)match[r] * SEQ_LEN);
        #pragma unroll
        for (int it = 0; it < ITERS; it++) {
            dst[it * THREADS + tid] = v[it];
        }
    }
}

extern "C" void kernel_launch(void* const* d_in, const int* in_sizes, int n_in,
                              void* d_out, int out_size)
{
    const int*   his = (const int*)d_in[0];    // [8192] int32
    const int*   cur = (const int*)d_in[1];    // [4096] int32
    const float* tsm = (const float*)d_in[2];  // [1024*1024] fp32
    float*       out = (float*)d_out;          // [4096*8192] fp32

    attn_time_dedup_kernel<<<T_DIM, THREADS>>>(his, cur, tsm, out);
}

// round 4
// speedup vs baseline: 1.2320x; 1.0693x over previous
#include <cuda_runtime.h>

#define SEQ_LEN   8192
#define STATE_LEN 4096
#define T_DIM     1024
#define THREADS   256
#define ITERS     8          // 8 iters x float4 x 256 threads = 8192 cols

// histogram of his (as float for direct FMA in the weighted sum)
__device__ float g_cnt[T_DIM];

// ---------------- Kernel 0: histogram of his ----------------
__global__ __launch_bounds__(1024)
void hist_kernel(const int* __restrict__ his)
{
    __shared__ int c[T_DIM];
    const int tid = threadIdx.x;
    c[tid] = 0;
    __syncthreads();
    #pragma unroll
    for (int k = 0; k < SEQ_LEN / 1024; k++)
        atomicAdd(&c[his[k * 1024 + tid]], 1);
    __syncthreads();
    g_cnt[tid] = (float)c[tid];
}

// ---------------- Kernel 1: per-row softmax via histogram + streamed gather ----------------
__global__ __launch_bounds__(THREADS)
void attn_time_fused_kernel(const int* __restrict__ his,
                            const int* __restrict__ cur,
                            const float* __restrict__ tsm,
                            float* __restrict__ out)
{
    __shared__ float w[T_DIM];               // exp(row - m), 4 KB
    __shared__ float red[THREADS / 32];

    const int tid = threadIdx.x;
    const int i   = blockIdx.x;
    const int t   = cur[i];                  // broadcast, L1/L2 hit

    // load tsm[t, :]: one float4 per thread (4 KB total)
    float4 r = reinterpret_cast<const float4*>(tsm + (size_t)t * T_DIM)[tid];

    // ---- block max over all 1024 values (valid upper bound for softmax shift) ----
    float m = fmaxf(fmaxf(r.x, r.y), fmaxf(r.z, r.w));
    #pragma unroll
    for (int off = 16; off; off >>= 1)
        m = fmaxf(m, __shfl_xor_sync(0xffffffff, m, off));
    if ((tid & 31) == 0) red[tid >> 5] = m;
    __syncthreads();
    float bm = red[0];
    #pragma unroll
    for (int k = 1; k < THREADS / 32; k++) bm = fmaxf(bm, red[k]);
    __syncthreads();                          // red[] reused below

    // ---- exp (1024 total) + histogram-weighted sum ----
    float4 cv = reinterpret_cast<const float4*>(g_cnt)[tid];   // L2-hit
    float4 ev;
    ev.x = __expf(r.x - bm);
    ev.y = __expf(r.y - bm);
    ev.z = __expf(r.z - bm);
    ev.w = __expf(r.w - bm);
    reinterpret_cast<float4*>(w)[tid] = ev;

    float s = cv.x * ev.x + cv.y * ev.y + cv.z * ev.z + cv.w * ev.w;
    #pragma unroll
    for (int off = 16; off; off >>= 1)
        s += __shfl_xor_sync(0xffffffff, s, off);
    if ((tid & 31) == 0) red[tid >> 5] = s;
    __syncthreads();                          // also publishes w[]
    float bs = 0.0f;
    #pragma unroll
    for (int k = 0; k < THREADS / 32; k++) bs += red[k];
    const float inv = 1.0f / bs;

    // ---- streamed gather + scale + store (no phase barriers, low regs) ----
    const int4* his4 = reinterpret_cast<const int4*>(his);     // L1-resident (32 KB)
    float4*     o    = reinterpret_cast<float4*>(out + (size_t)i * SEQ_LEN);
    #pragma unroll
    for (int it = 0; it < ITERS; it++) {
        int4 h = his4[it * THREADS + tid];
        float4 v;
        v.x = w[h.x] * inv;
        v.y = w[h.y] * inv;
        v.z = w[h.z] * inv;
        v.w = w[h.w] * inv;
        __stcs(&o[it * THREADS + tid], v);    // streaming store: don't pollute L2
    }
}

extern "C" void kernel_launch(void* const* d_in, const int* in_sizes, int n_in,
                              void* d_out, int out_size)
{
    const int*   his = (const int*)d_in[0];    // [8192] int32
    const int*   cur = (const int*)d_in[1];    // [4096] int32
    const float* tsm = (const float*)d_in[2];  // [1024*1024] fp32
    float*       out = (float*)d_out;          // [4096*8192] fp32

    hist_kernel<<<1, 1024>>>(his);
    attn_time_fused_kernel<<<STATE_LEN, THREADS>>>(his, cur, tsm, out);
}